// round 2
// baseline (speedup 1.0000x reference)
#include <cuda_runtime.h>
#include <math.h>

// Problem constants (match reference)
#define Hc 384
#define Wc 384
#define Bc 4
#define Mc 192
#define EPSc 1e-6f
#define MAXD 543.0580079f        // sqrt(384^2 + 384^2)
#define Cc (EPSc / MAXD)         // EPS / MAX_DIST

// Tiling
#define TPB 128
#define JT 3          // columns per thread: 128*3 = 384 = W
#define RR 6          // rows per block
#define MC 8          // m-chunk
#define TILES (Hc / RR)            // 64 row tiles per image
#define NBLOCKS (Bc * TILES)       // 256 blocks

// Scratch (no allocations allowed)
__device__ float g_t1part[NBLOCKS];
__device__ float g_ppart[NBLOCKS];
__device__ int   g_t2bits[Bc * Mc];   // float bits, atomicMin (nonneg floats)

__global__ void whd_init_kernel() {
    int i = threadIdx.x;
    if (i < Bc * Mc) g_t2bits[i] = 0x7F800000;   // +inf
}

__global__ __launch_bounds__(TPB) void whd_main_kernel(
    const float* __restrict__ prob,
    const float* __restrict__ gt,
    const float* __restrict__ osz)
{
    const int blk  = blockIdx.x;
    const int b    = blk / TILES;
    const int row0 = (blk % TILES) * RR;
    const int tid  = threadIdx.x;

    __shared__ float s_gy[Mc];
    __shared__ float s_gx[Mc];
    __shared__ float s_dy2[RR][Mc];
    __shared__ float s_red[8];

    const float fy = osz[b * 2 + 0] * (1.0f / (float)Hc);
    const float fx = osz[b * 2 + 1] * (1.0f / (float)Wc);

    for (int m = tid; m < Mc; m += TPB) {
        s_gy[m] = gt[(b * Mc + m) * 2 + 0] * fy;
        s_gx[m] = gt[(b * Mc + m) * 2 + 1] * fx;
    }
    __syncthreads();
    for (int idx = tid; idx < RR * Mc; idx += TPB) {
        int i = idx / Mc, m = idx - i * Mc;
        float dy = (float)(row0 + i) * fy - s_gy[m];
        s_dy2[i][m] = dy * dy;
    }

    // Per-pixel 1/w^2  (w = p^4 + EPS/MAX_DIST)
    const float* pimg = prob + (size_t)b * Hc * Wc;
    float xj[JT];
    float invw2[RR][JT];
#pragma unroll
    for (int jt = 0; jt < JT; jt++) xj[jt] = (float)(tid + jt * TPB) * fx;
#pragma unroll
    for (int i = 0; i < RR; i++) {
#pragma unroll
        for (int jt = 0; jt < JT; jt++) {
            float p  = pimg[(row0 + i) * Wc + tid + jt * TPB];
            float p2 = p * p;
            float w  = p2 * p2 + Cc;
            float iw = __fdividef(1.0f, w);
            invw2[i][jt] = iw * iw;
        }
    }
    __syncthreads();

    float pixmin[RR][JT];
#pragma unroll
    for (int i = 0; i < RR; i++)
#pragma unroll
        for (int jt = 0; jt < JT; jt++) pixmin[i][jt] = 3.0e38f;

    const int lane = tid & 31;

    for (int m0 = 0; m0 < Mc; m0 += MC) {
        float t2acc[MC];
        float dx2r[JT][MC];
#pragma unroll
        for (int mc = 0; mc < MC; mc++) {
            t2acc[mc] = 3.0e38f;
            float gx = s_gx[m0 + mc];
#pragma unroll
            for (int jt = 0; jt < JT; jt++) {
                float dx = xj[jt] - gx;
                dx2r[jt][mc] = dx * dx;
            }
        }
#pragma unroll
        for (int i = 0; i < RR; i++) {
#pragma unroll
            for (int mc = 0; mc < MC; mc++) {
                float dy2 = s_dy2[i][m0 + mc];
#pragma unroll
                for (int jt = 0; jt < JT; jt++) {
                    float d2 = dy2 + dx2r[jt][mc];
                    pixmin[i][jt] = fminf(pixmin[i][jt], d2);
                    float t = d2 * invw2[i][jt];
                    t2acc[mc] = fminf(t2acc[mc], t);
                }
            }
        }
        // warp-reduce each t2acc over 32 lanes, one atomic per (warp, m)
#pragma unroll
        for (int mc = 0; mc < MC; mc++) {
            float v = t2acc[mc];
            v = fminf(v, __shfl_xor_sync(0xffffffffu, v, 16));
            v = fminf(v, __shfl_xor_sync(0xffffffffu, v, 8));
            v = fminf(v, __shfl_xor_sync(0xffffffffu, v, 4));
            v = fminf(v, __shfl_xor_sync(0xffffffffu, v, 2));
            v = fminf(v, __shfl_xor_sync(0xffffffffu, v, 1));
            if (lane == mc)
                atomicMin(&g_t2bits[b * Mc + m0 + mc], __float_as_int(v));
        }
    }

    // term1 partials: sum p * sqrt(min_m d2), and sum p
    float t1p = 0.0f, pp = 0.0f;
#pragma unroll
    for (int i = 0; i < RR; i++) {
#pragma unroll
        for (int jt = 0; jt < JT; jt++) {
            float p = pimg[(row0 + i) * Wc + tid + jt * TPB];
            t1p += p * sqrtf(pixmin[i][jt]);
            pp  += p;
        }
    }
#pragma unroll
    for (int off = 16; off >= 1; off >>= 1) {
        t1p += __shfl_xor_sync(0xffffffffu, t1p, off);
        pp  += __shfl_xor_sync(0xffffffffu, pp,  off);
    }
    int w = tid >> 5;
    if (lane == 0) { s_red[w] = t1p; s_red[4 + w] = pp; }
    __syncthreads();
    if (tid == 0) {
        g_t1part[blk] = s_red[0] + s_red[1] + s_red[2] + s_red[3];
        g_ppart[blk]  = s_red[4] + s_red[5] + s_red[6] + s_red[7];
    }
}

__global__ void whd_final_kernel(float* __restrict__ out) {
    __shared__ float s2[Bc * Mc];
    __shared__ float s_im[Bc * 3];   // per-image: t1 num, p sum, t2 sum
    int tid = threadIdx.x;           // 768 threads

    // term2 values: sqrt of global min ratio, clipped
    if (tid < Bc * Mc) {
        float v = sqrtf(__int_as_float(g_t2bits[tid]));
        s2[tid] = fminf(v, MAXD);
    }
    __syncthreads();

    // deterministic per-image reduction of s2 (192 per image)
    {
        int b = tid / Mc, m = tid - b * Mc;
#pragma unroll
        for (int s = 96; s >= 3; s >>= 1) {
            if (m < s) s2[b * Mc + m] += s2[b * Mc + m + s];
            __syncthreads();
        }
        if (m == 0) s2[b * Mc] = s2[b * Mc] + s2[b * Mc + 1] + s2[b * Mc + 2];
    }

    // deterministic per-image reduction of t1/p partials.
    // Warp w (w<8) handles image w/2, half h=w&1: lanes cover 32 of the 64 blocks.
    int wrp = tid >> 5, lane = tid & 31;
    if (wrp < 8) {
        int b = wrp >> 1, h = wrp & 1;
        int idx = b * 64 + h * 32 + lane;
        float t1 = g_t1part[idx];
        float pp = g_ppart[idx];
#pragma unroll
        for (int off = 16; off >= 1; off >>= 1) {
            t1 += __shfl_xor_sync(0xffffffffu, t1, off);
            pp += __shfl_xor_sync(0xffffffffu, pp, off);
        }
        if (lane == 0) {
            if (h == 0) { s_im[b * 3 + 0] = t1; s_im[b * 3 + 1] = pp; }
        }
    }
    __syncthreads();
    if (wrp < 8 && lane == 0 && (wrp & 1) == 1) {
        // add second half deterministically (half 1 adds onto half 0's value)
        int b = wrp >> 1;
        float t1 = g_t1part[b * 64 + 32];  // recompute half-1 sums? no — use shuffle result
    }
    __syncthreads();
    // Simpler final path: thread 0 folds halves directly from warp results.
    // Store each warp's sums instead:
    __shared__ float s_w[8][2];
    if (wrp < 8) {
        int b = wrp >> 1;
        float t1 = g_t1part[b * 64 + (wrp & 1) * 32 + lane];
        float pp = g_ppart[b * 64 + (wrp & 1) * 32 + lane];
#pragma unroll
        for (int off = 16; off >= 1; off >>= 1) {
            t1 += __shfl_xor_sync(0xffffffffu, t1, off);
            pp += __shfl_xor_sync(0xffffffffu, pp, off);
        }
        if (lane == 0) { s_w[wrp][0] = t1; s_w[wrp][1] = pp; }
    }
    __syncthreads();
    if (tid == 0) {
        float res = 0.0f;
        for (int b = 0; b < Bc; b++) {
            float t1 = s_w[2 * b][0] + s_w[2 * b + 1][0];
            float pp = s_w[2 * b][1] + s_w[2 * b + 1][1];
            res += (t1 / (pp + EPSc)) * (1.0f / (float)Bc);
            res += (s2[b * Mc] * (1.0f / (float)Mc)) * (1.0f / (float)Bc);
        }
        out[0] = res;
    }
}

extern "C" void kernel_launch(void* const* d_in, const int* in_sizes, int n_in,
                              void* d_out, int out_size) {
    const float* prob = (const float*)d_in[0];
    const float* gt   = (const float*)d_in[1];
    const float* osz  = (const float*)d_in[2];
    float* out = (float*)d_out;

    whd_init_kernel<<<1, Bc * Mc>>>();
    whd_main_kernel<<<NBLOCKS, TPB>>>(prob, gt, osz);
    whd_final_kernel<<<1, 768>>>(out);
}